// round 5
// baseline (speedup 1.0000x reference)
#include <cuda_runtime.h>

typedef unsigned long long ULL;

// Problem constants (fixed by the dataset)
#define BATCH   256
#define PASTN   512
#define HID     512
#define FUT     64
#define TOTT    576          // PASTN + FUT
#define KK      256          // HID/2 (k-pairs)

// Launch config
#define NCTA    128          // 4 batch-tiles x 32 unit-tiles, <= resident SMs
#define NTHR    512
#define BTILE   64           // batches per CTA
#define UTILE   16           // hidden units per CTA (=> 64 gate rows)

// ---------------- device globals (scratch; no allocation allowed) -----------
// h double buffer, packed k-pairs: [p][kk][b] as one ULL = (h[b][2kk], h[b][2kk+1])
__device__ ULL g_hbuf[2 * KK * BATCH];
__device__ unsigned g_arrive;     // zero-initialized; returns to 0 after each run
__device__ unsigned g_release;    // monotone epoch counter (persists across replays)

// ---------------- helpers ---------------------------------------------------
__device__ __forceinline__ void fma2(ULL &d, ULL a, ULL b) {
    // packed dual-fp32 FMA (Blackwell FFMA2) - only reachable via PTX
    asm("fma.rn.f32x2 %0, %1, %2, %0;" : "+l"(d) : "l"(a), "l"(b));
}
__device__ __forceinline__ float lo2(ULL v) { return __uint_as_float((unsigned)(v & 0xffffffffu)); }
__device__ __forceinline__ float hi2(ULL v) { return __uint_as_float((unsigned)(v >> 32)); }
__device__ __forceinline__ ULL pack2(float a, float b) {
    return ((ULL)__float_as_uint(b) << 32) | (ULL)__float_as_uint(a);
}
__device__ __forceinline__ float sigf(float x) { return 1.0f / (1.0f + __expf(-x)); }

// Grid-wide barrier. All 128 CTAs are co-resident (1 CTA/SM). The gpu-scope
// __threadfence() both orders the h stores and (on sm_103a) invalidates L1D
// (CCTL.IVALL), so post-barrier cached h reads are fresh.
__device__ __forceinline__ void grid_barrier(unsigned target) {
    __syncthreads();
    if (threadIdx.x == 0) {
        __threadfence();
        unsigned prev = atomicAdd(&g_arrive, 1u);
        if (prev == NCTA - 1) {
            g_arrive = 0;
            __threadfence();
            *((volatile unsigned *)&g_release) = target;
        } else {
            while ((int)(*((volatile unsigned *)&g_release) - target) < 0) { }
        }
        __threadfence();   // both paths: flush/invalidate L1D before reading new h
    }
    __syncthreads();
}

// ---------------- kernel ----------------------------------------------------
extern __shared__ ULL wsm[];   // 16 units * 256 kk * 4 gates ULLs = 128 KB

__global__ void __launch_bounds__(NTHR, 1)
lstm_persist_kernel(const float *__restrict__ xin,    // [256][512][1]
                    const float *__restrict__ Wih,    // [2048][1]
                    const float *__restrict__ Whh,    // [2048][512]
                    const float *__restrict__ bih,    // [2048]
                    const float *__restrict__ bhh,    // [2048]
                    const float *__restrict__ Wdec,   // [1][512]
                    const float *__restrict__ bdec,   // [1]
                    float *__restrict__ out)          // [256][576][1]
{
    __shared__ float bsum_s[UTILE][4];
    __shared__ float wih_s[UTILE][4];
    __shared__ ULL   wdec_s[KK];          // W_dec packed in k-pairs
    __shared__ float part_s[8][64];       // decode partial sums
    __shared__ float ysm[64];             // decode result per local batch
    __shared__ unsigned ep_s;

    const int tid     = threadIdx.x;
    const int bt      = blockIdx.x & 3;        // batch tile 0..3
    const int jt      = blockIdx.x >> 2;       // unit tile 0..31
    const int b_local = tid & 63;
    const int ul      = tid >> 6;              // 0..7 -> owns units 2*ul, 2*ul+1
    const int bglob   = bt * BTILE + b_local;
    const int uu0     = 2 * ul;

    // ---- prologue: stage W_hh slice into smem, paired layout --------------
    // smem float layout: ((uu*KK + k/2)*4 + gate)*2 + (k&1)
    for (int idx = tid; idx < UTILE * 4 * HID; idx += NTHR) {
        int k  = idx & (HID - 1);
        int g  = (idx >> 9) & 3;
        int uu = idx >> 11;
        int n  = jt * UTILE + uu;
        float v = Whh[(g * HID + n) * HID + k];
        ((float *)wsm)[((uu * KK + (k >> 1)) * 4 + g) * 2 + (k & 1)] = v;
    }
    if (tid < UTILE * 4) {
        int uu = tid >> 2, g = tid & 3;
        int j  = g * HID + jt * UTILE + uu;
        bsum_s[uu][g] = bih[j] + bhh[j];
        wih_s[uu][g]  = Wih[j];              // FEAT = 1
    }
    for (int k = tid; k < HID; k += NTHR)
        ((float *)wdec_s)[k] = Wdec[k];
    if (tid == 0) ep_s = *((volatile unsigned *)&g_release);  // replay-safe epoch base

    // ---- init h0 = 0.01 (this thread's owned pair slot) -------------------
    {
        int kk_h = jt * 8 + ul;              // (jt*16 + 2*ul)/2
        g_hbuf[kk_h * BATCH + bglob] = pack2(0.01f, 0.01f);
    }
    float c0 = 0.01f, c1 = 0.01f;
    __syncthreads();

    unsigned epoch = ep_s;
    grid_barrier(++epoch);                   // h0 visible everywhere

    const float bdec_v = bdec[0];
    int p = 0;

    for (int t = 0; t < TOTT; ++t) {
        // input for this step
        float x = (t < PASTN) ? xin[bglob * PASTN + t] : ysm[b_local];

        // ---- gates: 2 units x 4 gates, packed-k dot over HID --------------
        const ULL *__restrict__ hp = g_hbuf + p * (KK * BATCH);
        ULL a00 = 0, a01 = 0, a02 = 0, a03 = 0;
        ULL a10 = 0, a11 = 0, a12 = 0, a13 = 0;
        const ulonglong2 *__restrict__ w0 =
            (const ulonglong2 *)(wsm + (size_t)uu0 * KK * 4);
        const ulonglong2 *__restrict__ w1 =
            (const ulonglong2 *)(wsm + (size_t)(uu0 + 1) * KK * 4);
#pragma unroll 4
        for (int kk = 0; kk < KK; ++kk) {
            ULL h2 = hp[kk * BATCH + bglob];       // coalesced 8B/lane, L1-cached
            ulonglong2 wa = w0[2 * kk], wb = w0[2 * kk + 1];   // LDS.128 broadcast
            ulonglong2 wc = w1[2 * kk], wd = w1[2 * kk + 1];
            fma2(a00, h2, wa.x); fma2(a01, h2, wa.y);
            fma2(a02, h2, wb.x); fma2(a03, h2, wb.y);
            fma2(a10, h2, wc.x); fma2(a11, h2, wc.y);
            fma2(a12, h2, wd.x); fma2(a13, h2, wd.y);
        }

        // ---- LSTM cell update (gates ordered i,f,g,o) ---------------------
        float h0v, h1v;
        {
            float gi = lo2(a00) + hi2(a00) + x * wih_s[uu0][0] + bsum_s[uu0][0];
            float gf = lo2(a01) + hi2(a01) + x * wih_s[uu0][1] + bsum_s[uu0][1];
            float gg = lo2(a02) + hi2(a02) + x * wih_s[uu0][2] + bsum_s[uu0][2];
            float go = lo2(a03) + hi2(a03) + x * wih_s[uu0][3] + bsum_s[uu0][3];
            c0  = sigf(gf) * c0 + sigf(gi) * tanhf(gg);
            h0v = sigf(go) * tanhf(c0);
        }
        {
            int uu1 = uu0 + 1;
            float gi = lo2(a10) + hi2(a10) + x * wih_s[uu1][0] + bsum_s[uu1][0];
            float gf = lo2(a11) + hi2(a11) + x * wih_s[uu1][1] + bsum_s[uu1][1];
            float gg = lo2(a12) + hi2(a12) + x * wih_s[uu1][2] + bsum_s[uu1][2];
            float go = lo2(a13) + hi2(a13) + x * wih_s[uu1][3] + bsum_s[uu1][3];
            c1  = sigf(gf) * c1 + sigf(gi) * tanhf(gg);
            h1v = sigf(go) * tanhf(c1);
        }

        const int p1 = p ^ 1;
        g_hbuf[p1 * (KK * BATCH) + (jt * 8 + ul) * BATCH + bglob] = pack2(h0v, h1v);

        grid_barrier(++epoch);               // new h complete & L1 invalidated

        // ---- decode y = h @ Wdec^T + bdec  (output; also next x in future phase)
        bool do_y = (jt == 0) || (t >= PASTN - 1);
        if (do_y) {
            const ULL *__restrict__ hq = g_hbuf + p1 * (KK * BATCH);
            ULL a = 0;
            int kk0 = ul * 32;
#pragma unroll 4
            for (int kk = kk0; kk < kk0 + 32; ++kk)
                fma2(a, hq[kk * BATCH + bglob], wdec_s[kk]);
            part_s[ul][b_local] = lo2(a) + hi2(a);
        }
        __syncthreads();
        if (do_y && tid < 64) {
            float s = bdec_v;
#pragma unroll
            for (int q = 0; q < 8; ++q) s += part_s[q][tid];
            ysm[tid] = s;
            if (jt == 0) out[(bt * 64 + tid) * TOTT + t] = s;
        }
        __syncthreads();
        p = p1;
    }
}

// ---------------- launch -----------------------------------------------------
extern "C" void kernel_launch(void *const *d_in, const int *in_sizes, int n_in,
                              void *d_out, int out_size) {
    const float *xin  = (const float *)d_in[0];   // input_seq [256,512,1]
    // d_in[1] = future_n (fixed 64, hardcoded)
    const float *Wih  = (const float *)d_in[2];   // [2048,1]
    const float *Whh  = (const float *)d_in[3];   // [2048,512]
    const float *bih  = (const float *)d_in[4];   // [2048]
    const float *bhh  = (const float *)d_in[5];   // [2048]
    const float *Wdec = (const float *)d_in[6];   // [1,512]
    const float *bdec = (const float *)d_in[7];   // [1]
    float *out = (float *)d_out;                  // [256,576,1]

    static_assert(UTILE * 4 * HID * 4 == 131072, "smem size");
    cudaFuncSetAttribute(lstm_persist_kernel,
                         cudaFuncAttributeMaxDynamicSharedMemorySize, 131072);

    lstm_persist_kernel<<<NCTA, NTHR, 131072>>>(xin, Wih, Whh, bih, bhh,
                                                Wdec, bdec, out);
    (void)in_sizes; (void)n_in; (void)out_size;
}

// round 6
// speedup vs baseline: 1.1342x; 1.1342x over previous
#include <cuda_runtime.h>

typedef unsigned long long ULL;

// Problem constants (fixed by the dataset)
#define BATCH   256
#define PASTN   512
#define HID     512
#define FUT     64
#define TOTT    576          // PASTN + FUT
#define KK      256          // HID/2 (k-pairs)

// Launch config
#define NCTA    128          // 4 batch-tiles x 32 unit-tiles
#define NTHR    512
#define BTILE   64           // batches per CTA
#define UTILE   16           // hidden units per CTA (=> 64 gate rows)
#define GRPC    32           // CTAs per barrier group (one batch-tile)

// ---------------- device globals (scratch; no allocation allowed) -----------
// h double buffer, packed k-pairs: [p][kk][b] as one ULL = (h[b][2kk], h[b][2kk+1])
__device__ ULL g_hbuf[2 * KK * BATCH];
__device__ float g_xT[PASTN * BATCH];                 // transposed input [t][b]
// 4 independent barrier groups (one per batch tile), 128B-strided counters
__device__ __align__(128) unsigned g_arrive[4 * 32];  // zero-init; returns to 0
__device__ __align__(128) unsigned g_release[4 * 32]; // monotone epochs

// ---------------- helpers ---------------------------------------------------
__device__ __forceinline__ void fma2(ULL &d, ULL a, ULL b) {
    // packed dual-fp32 FMA (Blackwell FFMA2) - only reachable via PTX
    asm("fma.rn.f32x2 %0, %1, %2, %0;" : "+l"(d) : "l"(a), "l"(b));
}
__device__ __forceinline__ float lo2(ULL v) { return __uint_as_float((unsigned)(v & 0xffffffffu)); }
__device__ __forceinline__ float hi2(ULL v) { return __uint_as_float((unsigned)(v >> 32)); }
__device__ __forceinline__ ULL pack2(float a, float b) {
    return ((ULL)__float_as_uint(b) << 32) | (ULL)__float_as_uint(a);
}
__device__ __forceinline__ float sigf(float x) { return 1.0f / (1.0f + __expf(-x)); }

// Group-wide barrier over GRPC co-resident CTAs. The gpu-scope __threadfence()
// orders the h stores / REDs and (sm_103a) invalidates L1D (CCTL.IVALL) so
// post-barrier cached h reads are fresh.
__device__ __forceinline__ void group_barrier(int grp, unsigned target) {
    __syncthreads();
    if (threadIdx.x == 0) {
        __threadfence();
        unsigned prev = atomicAdd(&g_arrive[grp], 1u);
        if (prev == GRPC - 1) {
            g_arrive[grp] = 0;
            __threadfence();
            *((volatile unsigned *)&g_release[grp]) = target;
        } else {
            while ((int)(*((volatile unsigned *)&g_release[grp]) - target) < 0) { }
        }
        __threadfence();   // both paths: flush/invalidate L1D before reading new h
    }
    __syncthreads();
}

// ---------------- kernel ----------------------------------------------------
extern __shared__ ULL wsm[];   // 16 units * 256 kk * 4 gates ULLs = 128 KB

__global__ void __launch_bounds__(NTHR, 1)
lstm_persist_kernel(const float *__restrict__ xin,    // [256][512][1]
                    const float *__restrict__ Wih,    // [2048][1]
                    const float *__restrict__ Whh,    // [2048][512]
                    const float *__restrict__ bih,    // [2048]
                    const float *__restrict__ bhh,    // [2048]
                    const float *__restrict__ Wdec,   // [1][512]
                    const float *__restrict__ bdec,   // [1]
                    float *__restrict__ out)          // [256][576][1]
{
    __shared__ float bsum_s[UTILE][4];
    __shared__ float wih_s[UTILE][4];
    __shared__ float part_s[8][64];       // decode partial sums
    __shared__ unsigned ep_s;

    const int tid     = threadIdx.x;
    const int bt      = blockIdx.x & 3;        // batch tile 0..3
    const int jt      = blockIdx.x >> 2;       // unit tile 0..31
    const int b_local = tid & 63;
    const int ul      = tid >> 6;              // 0..7 -> owns units 2*ul, 2*ul+1
    const int bglob   = bt * BTILE + b_local;
    const int uu0     = 2 * ul;
    const int grp     = bt * 32;               // barrier-group slot (128B strided)

    // ---- prologue: stage W_hh slice into smem, paired layout --------------
    // smem float layout: ((uu*KK + k/2)*4 + gate)*2 + (k&1)
    for (int idx = tid; idx < UTILE * 4 * HID; idx += NTHR) {
        int k  = idx & (HID - 1);
        int g  = (idx >> 9) & 3;
        int uu = idx >> 11;
        int n  = jt * UTILE + uu;
        float v = Whh[(g * HID + n) * HID + k];
        ((float *)wsm)[((uu * KK + (k >> 1)) * 4 + g) * 2 + (k & 1)] = v;
    }
    if (tid < UTILE * 4) {
        int uu = tid >> 2, g = tid & 3;
        int j  = g * HID + jt * UTILE + uu;
        bsum_s[uu][g] = bih[j] + bhh[j];
        wih_s[uu][g]  = Wih[j];              // FEAT = 1
    }
    const float bdec_v = bdec[0];
    const float wd0 = Wdec[jt * UTILE + uu0];
    const float wd1 = Wdec[jt * UTILE + uu0 + 1];

    // transpose input: x[t][b] for coalesced per-step loads
    for (int i = blockIdx.x * NTHR + tid; i < PASTN * BATCH; i += NCTA * NTHR) {
        int t = i >> 8, b = i & (BATCH - 1);
        g_xT[i] = xin[b * PASTN + t];
    }
    // init output slice of this batch tile with b_dec (atomics accumulate onto it)
    for (int i = jt * NTHR + tid; i < BTILE * TOTT; i += 32 * NTHR) {
        int bl = i / TOTT, tt = i - bl * TOTT;
        out[(bt * BTILE + bl) * TOTT + tt] = bdec_v;
    }

    if (tid == 0) ep_s = *((volatile unsigned *)&g_release[grp]);  // replay-safe base

    // ---- init h0 = 0.01 (this thread's owned pair slot) -------------------
    g_hbuf[(jt * 8 + ul) * BATCH + bglob] = pack2(0.01f, 0.01f);
    float c0 = 0.01f, c1 = 0.01f;
    __syncthreads();

    unsigned epoch = ep_s;
    group_barrier(grp, ++epoch);             // h0, xT, out-init visible in group

    int p = 0;

    for (int t = 0; t < TOTT; ++t) {
        // input for this step (future phase: y reduced into out at step t-1)
        float x = (t < PASTN) ? g_xT[t * BATCH + bglob]
                              : out[bglob * TOTT + (t - 1)];

        // ---- gates: 2 units x 4 gates, packed-k dot over HID --------------
        const ULL *__restrict__ hp = g_hbuf + p * (KK * BATCH) + bglob;
        ULL a00 = 0, a01 = 0, a02 = 0, a03 = 0;
        ULL a10 = 0, a11 = 0, a12 = 0, a13 = 0;
        const ulonglong2 *__restrict__ w0 =
            (const ulonglong2 *)(wsm + (size_t)uu0 * KK * 4);
        const ulonglong2 *__restrict__ w1 =
            (const ulonglong2 *)(wsm + (size_t)(uu0 + 1) * KK * 4);
#pragma unroll 8
        for (int kk = 0; kk < KK; ++kk) {
            ULL h2 = hp[kk * BATCH];               // coalesced 8B/lane, L1-cached
            ulonglong2 wa = w0[2 * kk], wb = w0[2 * kk + 1];   // LDS.128 broadcast
            ulonglong2 wc = w1[2 * kk], wd = w1[2 * kk + 1];
            fma2(a00, h2, wa.x); fma2(a01, h2, wa.y);
            fma2(a02, h2, wb.x); fma2(a03, h2, wb.y);
            fma2(a10, h2, wc.x); fma2(a11, h2, wc.y);
            fma2(a12, h2, wd.x); fma2(a13, h2, wd.y);
        }

        // ---- LSTM cell update (gates ordered i,f,g,o) ---------------------
        float h0v, h1v;
        {
            float gi = lo2(a00) + hi2(a00) + x * wih_s[uu0][0] + bsum_s[uu0][0];
            float gf = lo2(a01) + hi2(a01) + x * wih_s[uu0][1] + bsum_s[uu0][1];
            float gg = lo2(a02) + hi2(a02) + x * wih_s[uu0][2] + bsum_s[uu0][2];
            float go = lo2(a03) + hi2(a03) + x * wih_s[uu0][3] + bsum_s[uu0][3];
            c0  = sigf(gf) * c0 + sigf(gi) * tanhf(gg);
            h0v = sigf(go) * tanhf(c0);
        }
        {
            int uu1 = uu0 + 1;
            float gi = lo2(a10) + hi2(a10) + x * wih_s[uu1][0] + bsum_s[uu1][0];
            float gf = lo2(a11) + hi2(a11) + x * wih_s[uu1][1] + bsum_s[uu1][1];
            float gg = lo2(a12) + hi2(a12) + x * wih_s[uu1][2] + bsum_s[uu1][2];
            float go = lo2(a13) + hi2(a13) + x * wih_s[uu1][3] + bsum_s[uu1][3];
            c1  = sigf(gf) * c1 + sigf(gi) * tanhf(gg);
            h1v = sigf(go) * tanhf(c1);
        }

        const int p1 = p ^ 1;
        g_hbuf[p1 * (KK * BATCH) + (jt * 8 + ul) * BATCH + bglob] = pack2(h0v, h1v);

        // ---- decode contribution from registers (no h re-read) ------------
        part_s[ul][b_local] = h0v * wd0 + h1v * wd1;
        __syncthreads();
        if (tid < 64) {
            float s = part_s[0][tid];
#pragma unroll
            for (int q = 1; q < 8; ++q) s += part_s[q][tid];
            atomicAdd(&out[(bt * BTILE + tid) * TOTT + t], s);   // REDG, no return
        }

        group_barrier(grp, ++epoch);         // h + y complete, L1 invalidated
        p = p1;
    }
}

// ---------------- launch -----------------------------------------------------
extern "C" void kernel_launch(void *const *d_in, const int *in_sizes, int n_in,
                              void *d_out, int out_size) {
    const float *xin  = (const float *)d_in[0];   // input_seq [256,512,1]
    // d_in[1] = future_n (fixed 64, hardcoded)
    const float *Wih  = (const float *)d_in[2];   // [2048,1]
    const float *Whh  = (const float *)d_in[3];   // [2048,512]
    const float *bih  = (const float *)d_in[4];   // [2048]
    const float *bhh  = (const float *)d_in[5];   // [2048]
    const float *Wdec = (const float *)d_in[6];   // [1,512]
    const float *bdec = (const float *)d_in[7];   // [1]
    float *out = (float *)d_out;                  // [256,576,1]

    static_assert(UTILE * 4 * HID * 4 == 131072, "smem size");
    cudaFuncSetAttribute(lstm_persist_kernel,
                         cudaFuncAttributeMaxDynamicSharedMemorySize, 131072);

    lstm_persist_kernel<<<NCTA, NTHR, 131072>>>(xin, Wih, Whh, bih, bhh,
                                                Wdec, bdec, out);
    (void)in_sizes; (void)n_in; (void)out_size;
}